// round 12
// baseline (speedup 1.0000x reference)
#include <cuda_runtime.h>
#include <cuda_bf16.h>
#include <cstdint>

// Problem: B=256, N=64, d=64. Outputs concatenated: alphas [B,N,N,1] then value [B,N,N,64].
constexpr int Bn = 256;
constexpr int Nn = 64;
constexpr int Dn = 64;
constexpr float NEG_SLOPE = 0.01f;

// smem layout (bytes)
constexpr int OFF_WB = 0;                        // 64 f32
constexpr int OFF_AW = 256;                      // 64 f32
constexpr int OFF_XI = 512;                      // 8 i-rows fp32, stride 72: 2304
constexpr int OFF_XJ = 2816;                     // 8 j-rows fp32, stride 72: 2304
constexpr int OFF_EJ = 5120;                     // E[j] frag table fp32 (swizzled, 8 rows): 2048
constexpr int OFF_SB = 7168;                     // W frag table bf16 hi/lo (swizzled, 64 rows): 16384
constexpr int SMEM_TOTAL = OFF_SB + 16384;       // 23552 B

// upper-triangle 8x8-block enumeration (36 blocks)
static __device__ const unsigned char cBI[36] = {
    0,0,0,0,0,0,0,0, 1,1,1,1,1,1,1, 2,2,2,2,2,2, 3,3,3,3,3, 4,4,4,4, 5,5,5, 6,6, 7};
static __device__ const unsigned char cBJ[36] = {
    0,1,2,3,4,5,6,7, 1,2,3,4,5,6,7, 2,3,4,5,6,7, 3,4,5,6,7, 4,5,6,7, 5,6,7, 6,7, 7};

static __device__ __forceinline__ void mma_bf16(float* c, const uint32_t* a, const uint32_t* b) {
    asm volatile(
        "mma.sync.aligned.m16n8k16.row.col.f32.bf16.bf16.f32 "
        "{%0,%1,%2,%3}, {%4,%5,%6,%7}, {%8,%9}, {%0,%1,%2,%3};"
        : "+f"(c[0]), "+f"(c[1]), "+f"(c[2]), "+f"(c[3])
        : "r"(a[0]), "r"(a[1]), "r"(a[2]), "r"(a[3]), "r"(b[0]), "r"(b[1]));
}

static __device__ __forceinline__ void split2(float a, float b, uint32_t& hi, uint32_t& lo) {
    __nv_bfloat162 h = __floats2bfloat162_rn(a, b);
    uint32_t hu = *reinterpret_cast<uint32_t*>(&h);
    float hax = __uint_as_float(hu << 16);
    float hay = __uint_as_float(hu & 0xFFFF0000u);
    __nv_bfloat162 l = __floats2bfloat162_rn(a - hax, b - hay);
    hi = hu;
    lo = *reinterpret_cast<uint32_t*>(&l);
}

static __device__ __forceinline__ void stcs4(float* p, float4 v) {
    asm volatile("st.global.cs.v4.f32 [%0], {%1,%2,%3,%4};"
                 :: "l"(p), "f"(v.x), "f"(v.y), "f"(v.z), "f"(v.w) : "memory");
}

// 64-row frag table swizzle (W table): ks block stride 4096B
static __device__ __forceinline__ uint32_t swzoff(int j, int q, int ks) {
    uint32_t u = (uint32_t)(j * 4 + q);
    uint32_t t = (((uint32_t)j & 3u) << 1) | (((uint32_t)ks >> 1) & 1u);
    return ((uint32_t)ks << 12) + ((u ^ t) << 4);
}
// 8-row frag table swizzle (E[j] table): ks block stride 512B
static __device__ __forceinline__ uint32_t swz8(int j, int q, int ks) {
    uint32_t u = (uint32_t)(j * 4 + q);
    uint32_t t = (((uint32_t)j & 3u) << 1) | (((uint32_t)ks >> 1) & 1u);
    return ((uint32_t)ks << 9) + ((u ^ t) << 4);
}

// One CTA: (b, triangle block t -> (bi, bj)). 128 threads / 4 warps.
// Computes the 64 pairs (i in bi-block, j in bj-block): value rows (+mirror),
// logits (+mirror) into the alphas buffer as scratch. Warp w: i-pair (2w,2w+1) x 8 j.
__global__ __launch_bounds__(128, 5)
void afm_pair(const float* __restrict__ emb,
              const float* __restrict__ wW,
              const float* __restrict__ wb,
              const float* __restrict__ aW,
              float* __restrict__ logits,   // B*N*N scratch (= alphas buffer)
              float* __restrict__ outV)
{
    extern __shared__ __align__(16) char smem[];
    const int t   = blockIdx.x;   // 0..35
    const int b   = blockIdx.y;   // 0..255
    const int bi  = cBI[t];
    const int bj  = cBJ[t];
    const bool diag = (bi == bj);
    const int tx  = threadIdx.x;
    const int wid = tx >> 5;      // 0..3
    const int lid = tx & 31;
    const int g   = lid >> 2;     // 0..7
    const int q   = lid & 3;      // 0..3

    float* sWB = reinterpret_cast<float*>(smem + OFF_WB);
    float* sAW = reinterpret_cast<float*>(smem + OFF_AW);
    float* sXI = reinterpret_cast<float*>(smem + OFF_XI);
    float* sXJ = reinterpret_cast<float*>(smem + OFF_XJ);

    const float* embB = emb + (size_t)b * Nn * Dn;

    if (tx < 64) { sWB[tx] = wb[tx]; sAW[tx] = aW[tx]; }
    // natural copies of the block's 8 i-rows and 8 j-rows
    {
        const int row = tx >> 4;   // 0..7
        const int c4  = tx & 15;
        reinterpret_cast<float4*>(sXI + row * 72)[c4] =
            reinterpret_cast<const float4*>(embB + (bi * 8 + row) * Dn)[c4];
        reinterpret_cast<float4*>(sXJ + row * 72)[c4] =
            reinterpret_cast<const float4*>(embB + (bj * 8 + row) * Dn)[c4];
    }

    // E[j] frag table (8 rows), fp32, swizzled
    if (tx < 32) {
        const int row = tx >> 2;   // 0..7
        const int qt  = tx & 3;    // ks block
        float4 e[4];
        const float4* src = reinterpret_cast<const float4*>(
            embB + (bj * 8 + row) * Dn + qt * 16);
        #pragma unroll
        for (int k = 0; k < 4; k++) e[k] = src[k];
        #pragma unroll
        for (int qq = 0; qq < 4; qq++) {
            float4 va = e[qq >> 1];
            float4 vb = e[2 + (qq >> 1)];
            float ax = (qq & 1) ? va.z : va.x;
            float ay = (qq & 1) ? va.w : va.y;
            float bx = (qq & 1) ? vb.z : vb.x;
            float by = (qq & 1) ? vb.w : vb.y;
            *reinterpret_cast<float4*>(smem + OFF_EJ + swz8(row, qq, qt)) =
                make_float4(ax, ay, bx, by);
        }
    }

    // W frag table (64 rows), bf16 hi/lo, swizzled
    {
        const int jr = tx >> 1;    // 0..63
        const int hf = tx & 1;
        const float4* src = reinterpret_cast<const float4*>(wW + jr * Dn + hf * 32);
        uint32_t hu[16], lu[16];
        #pragma unroll
        for (int k = 0; k < 8; k++) {
            float4 w4 = src[k];
            split2(w4.x, w4.y, hu[2 * k],     lu[2 * k]);
            split2(w4.z, w4.w, hu[2 * k + 1], lu[2 * k + 1]);
        }
        #pragma unroll
        for (int s = 0; s < 2; s++) {
            const int ks = 2 * hf + s;
            #pragma unroll
            for (int qq = 0; qq < 4; qq++) {
                const int c0 = 8 * s + qq;
                *reinterpret_cast<uint4*>(smem + OFF_SB + swzoff(jr, qq, ks)) =
                    make_uint4(hu[c0], hu[c0 + 4], lu[c0], lu[c0 + 4]);
            }
        }
    }
    __syncthreads();

    // ---- value phase: pair r = (i = r>>3, j = r&7), half-row hf ----
    {
        const int r  = tx >> 1;    // 0..63
        const int hf = tx & 1;
        const int i  = r >> 3;
        const int j  = r & 7;
        const int iG = bi * 8 + i;
        const int jG = bj * 8 + j;
        const float4* xj = reinterpret_cast<const float4*>(sXJ + j * 72 + hf * 32);
        const float4* xi = reinterpret_cast<const float4*>(sXI + i * 72 + hf * 32);
        float* oV = outV + ((((size_t)b * Nn + iG) * Nn + jG) * Dn + hf * 32);
        float* oM = outV + ((((size_t)b * Nn + jG) * Nn + iG) * Dn + hf * 32);
        #pragma unroll
        for (int k = 0; k < 8; k++) {
            float4 a4 = xj[k];
            float4 b4 = xi[k];
            float4 v = make_float4(a4.x * b4.x, a4.y * b4.y, a4.z * b4.z, a4.w * b4.w);
            stcs4(oV + 4 * k, v);
            if (!diag) stcs4(oM + 4 * k, v);
        }
    }

    // ---- GEMM: warp w -> rows (i0=2w, j_g) and (i1=2w+1, j_g), N=64 ----
    const float* sXi0 = sXI + (2 * wid) * 72;
    const float* sXi1 = sXi0 + 72;

    float acc[8][4];
    #pragma unroll
    for (int nt = 0; nt < 8; nt++)
        #pragma unroll
        for (int r = 0; r < 4; r++) acc[nt][r] = 0.0f;

    #pragma unroll
    for (int ks = 0; ks < 4; ks++) {
        const int kc = ks * 16 + 2 * q;
        const float2 xa0 = *reinterpret_cast<const float2*>(sXi0 + kc);
        const float2 xc0 = *reinterpret_cast<const float2*>(sXi0 + kc + 8);
        const float2 xa1 = *reinterpret_cast<const float2*>(sXi1 + kc);
        const float2 xc1 = *reinterpret_cast<const float2*>(sXi1 + kc + 8);

        const float4 f0 = *reinterpret_cast<const float4*>(smem + OFF_EJ + swz8(g, q, ks));
        uint32_t ah[4], al[4];
        split2(f0.x * xa0.x, f0.y * xa0.y, ah[0], al[0]);   // row g   (i0), k-lo
        split2(f0.x * xa1.x, f0.y * xa1.y, ah[1], al[1]);   // row g+8 (i1), k-lo
        split2(f0.z * xc0.x, f0.w * xc0.y, ah[2], al[2]);   // row g   (i0), k-hi
        split2(f0.z * xc1.x, f0.w * xc1.y, ah[3], al[3]);   // row g+8 (i1), k-hi

        #pragma unroll
        for (int nt = 0; nt < 8; nt++) {
            const uint4 bv = *reinterpret_cast<const uint4*>(
                smem + OFF_SB + swzoff(nt * 8 + g, q, ks));
            uint32_t bh[2] = {bv.x, bv.y};
            uint32_t bl[2] = {bv.z, bv.w};
            mma_bf16(acc[nt], ah, bh);
            mma_bf16(acc[nt], ah, bl);
            mma_bf16(acc[nt], al, bh);
        }
    }

    // ---- epilogue: logits for rows (i0,j_g) [h=0] and (i1,j_g) [h=1] ----
    #pragma unroll
    for (int h = 0; h < 2; h++) {
        float pl = 0.0f;
        #pragma unroll
        for (int nt = 0; nt < 8; nt++) {
            const int e0 = nt * 8 + 2 * q;
            float q0 = acc[nt][2 * h + 0] + sWB[e0];
            float q1 = acc[nt][2 * h + 1] + sWB[e0 + 1];
            q0 = (q0 >= 0.0f) ? q0 : NEG_SLOPE * q0;
            q1 = (q1 >= 0.0f) ? q1 : NEG_SLOPE * q1;
            pl = fmaf(sAW[e0], q0, pl);
            pl = fmaf(sAW[e0 + 1], q1, pl);
        }
        pl += __shfl_xor_sync(0xffffffffu, pl, 1);
        pl += __shfl_xor_sync(0xffffffffu, pl, 2);
        if (q == 0) {
            const int iG = bi * 8 + 2 * wid + h;
            const int jG = bj * 8 + g;
            logits[((size_t)b * Nn + iG) * Nn + jG] = pl;
            if (!diag) logits[((size_t)b * Nn + jG) * Nn + iG] = pl;
        }
    }
}

// in-place softmax over last dim of logits [B,N,N]; warp per (b,i) row
__global__ __launch_bounds__(128)
void afm_softmax(float* __restrict__ logits)
{
    const int i = blockIdx.x * 4 + (threadIdx.x >> 5);
    const int b = blockIdx.y;
    const int lid = threadIdx.x & 31;
    float* row = logits + ((size_t)b * Nn + i) * Nn;
    float v0 = row[lid];
    float v1 = row[lid + 32];
    float m = fmaxf(v0, v1);
    #pragma unroll
    for (int msk = 16; msk >= 1; msk >>= 1)
        m = fmaxf(m, __shfl_xor_sync(0xffffffffu, m, msk));
    float e0 = __expf(v0 - m);
    float e1 = __expf(v1 - m);
    float s = e0 + e1;
    #pragma unroll
    for (int msk = 16; msk >= 1; msk >>= 1)
        s += __shfl_xor_sync(0xffffffffu, s, msk);
    const float inv = 1.0f / s;
    row[lid]      = e0 * inv;
    row[lid + 32] = e1 * inv;
}

extern "C" void kernel_launch(void* const* d_in, const int* in_sizes, int n_in,
                              void* d_out, int out_size)
{
    (void)in_sizes; (void)n_in; (void)out_size;
    const float* emb = (const float*)d_in[0];
    const float* wW  = (const float*)d_in[1];
    const float* wb  = (const float*)d_in[2];
    const float* aW  = (const float*)d_in[3];
    // d_in[4] = a_b: constant shift, cancels in softmax

    float* out  = (float*)d_out;
    float* outA = out;                          // logits scratch -> alphas
    float* outV = out + (size_t)Bn * Nn * Nn;

    cudaFuncSetAttribute(afm_pair, cudaFuncAttributeMaxDynamicSharedMemorySize, SMEM_TOTAL);
    dim3 grid1(36, Bn);
    afm_pair<<<grid1, 128, SMEM_TOTAL>>>(emb, wW, wb, aW, outA, outV);
    dim3 grid2(16, Bn);
    afm_softmax<<<grid2, 128>>>(outA);
}

// round 13
// speedup vs baseline: 1.0529x; 1.0529x over previous
#include <cuda_runtime.h>
#include <cuda_bf16.h>
#include <cstdint>

// Problem: B=256, N=64, d=64. Outputs concatenated: alphas [B,N,N,1] then value [B,N,N,64].
constexpr int Bn = 256;
constexpr int Nn = 64;
constexpr int Dn = 64;
constexpr float NEG_SLOPE = 0.01f;

// smem layout (bytes)
constexpr int OFF_WB = 0;                        // 64 f32
constexpr int OFF_AW = 256;                      // 64 f32
constexpr int OFF_XI = 512;                      // 8 i-rows fp32, stride 72: 2304
constexpr int OFF_XJ = 2816;                     // 8 j-rows fp32, stride 72: 2304
constexpr int OFF_EJ = 5120;                     // E[j] frag table fp32 (swizzled, 8 rows): 2048
constexpr int OFF_SB = 7168;                     // W frag table bf16 hi/lo (swizzled, 64 rows): 16384
constexpr int SMEM_TOTAL = OFF_SB + 16384;       // 23552 B

// upper-triangle 8x8-block enumeration (36 blocks)
static __device__ const unsigned char cBI[36] = {
    0,0,0,0,0,0,0,0, 1,1,1,1,1,1,1, 2,2,2,2,2,2, 3,3,3,3,3, 4,4,4,4, 5,5,5, 6,6, 7};
static __device__ const unsigned char cBJ[36] = {
    0,1,2,3,4,5,6,7, 1,2,3,4,5,6,7, 2,3,4,5,6,7, 3,4,5,6,7, 4,5,6,7, 5,6,7, 6,7, 7};

static __device__ __forceinline__ void mma_bf16(float* c, const uint32_t* a, const uint32_t* b) {
    asm volatile(
        "mma.sync.aligned.m16n8k16.row.col.f32.bf16.bf16.f32 "
        "{%0,%1,%2,%3}, {%4,%5,%6,%7}, {%8,%9}, {%0,%1,%2,%3};"
        : "+f"(c[0]), "+f"(c[1]), "+f"(c[2]), "+f"(c[3])
        : "r"(a[0]), "r"(a[1]), "r"(a[2]), "r"(a[3]), "r"(b[0]), "r"(b[1]));
}

static __device__ __forceinline__ void split2(float a, float b, uint32_t& hi, uint32_t& lo) {
    __nv_bfloat162 h = __floats2bfloat162_rn(a, b);
    uint32_t hu = *reinterpret_cast<uint32_t*>(&h);
    float hax = __uint_as_float(hu << 16);
    float hay = __uint_as_float(hu & 0xFFFF0000u);
    __nv_bfloat162 l = __floats2bfloat162_rn(a - hax, b - hay);
    hi = hu;
    lo = *reinterpret_cast<uint32_t*>(&l);
}

static __device__ __forceinline__ void stcs4(float* p, float4 v) {
    asm volatile("st.global.cs.v4.f32 [%0], {%1,%2,%3,%4};"
                 :: "l"(p), "f"(v.x), "f"(v.y), "f"(v.z), "f"(v.w) : "memory");
}

// 64-row frag table swizzle (W table): ks block stride 4096B
static __device__ __forceinline__ uint32_t swzoff(int j, int q, int ks) {
    uint32_t u = (uint32_t)(j * 4 + q);
    uint32_t t = (((uint32_t)j & 3u) << 1) | (((uint32_t)ks >> 1) & 1u);
    return ((uint32_t)ks << 12) + ((u ^ t) << 4);
}
// 8-row frag table swizzle (E[j] table): ks block stride 512B
static __device__ __forceinline__ uint32_t swz8(int j, int q, int ks) {
    uint32_t u = (uint32_t)(j * 4 + q);
    uint32_t t = (((uint32_t)j & 3u) << 1) | (((uint32_t)ks >> 1) & 1u);
    return ((uint32_t)ks << 9) + ((u ^ t) << 4);
}

// One CTA: (b, 4 triangle blocks t = x + 9*tt). 128 threads / 4 warps.
// W frag table filled once per CTA; per block: small fills, value(+mirror),
// GEMM (warp w -> i rows 2w,2w+1 vs 8 j), logits(+mirror) to scratch.
__global__ __launch_bounds__(128, 5)
void afm_pair(const float* __restrict__ emb,
              const float* __restrict__ wW,
              const float* __restrict__ wb,
              const float* __restrict__ aW,
              float* __restrict__ logits,   // B*N*N scratch (= alphas buffer)
              float* __restrict__ outV)
{
    extern __shared__ __align__(16) char smem[];
    const int xb  = blockIdx.x;   // 0..8
    const int b   = blockIdx.y;   // 0..255
    const int tx  = threadIdx.x;
    const int wid = tx >> 5;      // 0..3
    const int lid = tx & 31;
    const int g   = lid >> 2;     // 0..7
    const int q   = lid & 3;      // 0..3

    float* sWB = reinterpret_cast<float*>(smem + OFF_WB);
    float* sAW = reinterpret_cast<float*>(smem + OFF_AW);
    float* sXI = reinterpret_cast<float*>(smem + OFF_XI);
    float* sXJ = reinterpret_cast<float*>(smem + OFF_XJ);

    const float* embB = emb + (size_t)b * Nn * Dn;

    if (tx < 64) { sWB[tx] = wb[tx]; sAW[tx] = aW[tx]; }

    // ---- W frag table (64 rows), bf16 hi/lo, swizzled — ONCE per CTA ----
    {
        const int jr = tx >> 1;    // 0..63
        const int hf = tx & 1;
        const float4* src = reinterpret_cast<const float4*>(wW + jr * Dn + hf * 32);
        uint32_t hu[16], lu[16];
        #pragma unroll
        for (int k = 0; k < 8; k++) {
            float4 w4 = src[k];
            split2(w4.x, w4.y, hu[2 * k],     lu[2 * k]);
            split2(w4.z, w4.w, hu[2 * k + 1], lu[2 * k + 1]);
        }
        #pragma unroll
        for (int s = 0; s < 2; s++) {
            const int ks = 2 * hf + s;
            #pragma unroll
            for (int qq = 0; qq < 4; qq++) {
                const int c0 = 8 * s + qq;
                *reinterpret_cast<uint4*>(smem + OFF_SB + swzoff(jr, qq, ks)) =
                    make_uint4(hu[c0], hu[c0 + 4], lu[c0], lu[c0 + 4]);
            }
        }
    }

    #pragma unroll 1
    for (int tt = 0; tt < 4; tt++) {
        const int t  = xb + 9 * tt;   // 0..35
        const int bi = cBI[t];
        const int bj = cBJ[t];
        const bool diag = (bi == bj);

        // ---- per-block fills: 8 i-rows, 8 j-rows, EJ frag table ----
        {
            const int row = tx >> 4;   // 0..7
            const int c4  = tx & 15;
            reinterpret_cast<float4*>(sXI + row * 72)[c4] =
                reinterpret_cast<const float4*>(embB + (bi * 8 + row) * Dn)[c4];
            reinterpret_cast<float4*>(sXJ + row * 72)[c4] =
                reinterpret_cast<const float4*>(embB + (bj * 8 + row) * Dn)[c4];
        }
        if (tx < 32) {
            const int row = tx >> 2;   // 0..7
            const int qt  = tx & 3;    // ks block
            float4 e[4];
            const float4* src = reinterpret_cast<const float4*>(
                embB + (bj * 8 + row) * Dn + qt * 16);
            #pragma unroll
            for (int k = 0; k < 4; k++) e[k] = src[k];
            #pragma unroll
            for (int qq = 0; qq < 4; qq++) {
                float4 va = e[qq >> 1];
                float4 vb = e[2 + (qq >> 1)];
                float ax = (qq & 1) ? va.z : va.x;
                float ay = (qq & 1) ? va.w : va.y;
                float bx = (qq & 1) ? vb.z : vb.x;
                float by = (qq & 1) ? vb.w : vb.y;
                *reinterpret_cast<float4*>(smem + OFF_EJ + swz8(row, qq, qt)) =
                    make_float4(ax, ay, bx, by);
            }
        }
        __syncthreads();

        // ---- value phase: pair r = (i = r>>3, j = r&7), half-row hf ----
        {
            const int r  = tx >> 1;    // 0..63
            const int hf = tx & 1;
            const int i  = r >> 3;
            const int j  = r & 7;
            const int iG = bi * 8 + i;
            const int jG = bj * 8 + j;
            const float4* xj = reinterpret_cast<const float4*>(sXJ + j * 72 + hf * 32);
            const float4* xi = reinterpret_cast<const float4*>(sXI + i * 72 + hf * 32);
            float* oV = outV + ((((size_t)b * Nn + iG) * Nn + jG) * Dn + hf * 32);
            float* oM = outV + ((((size_t)b * Nn + jG) * Nn + iG) * Dn + hf * 32);
            #pragma unroll
            for (int k = 0; k < 8; k++) {
                float4 a4 = xj[k];
                float4 b4 = xi[k];
                float4 v = make_float4(a4.x * b4.x, a4.y * b4.y, a4.z * b4.z, a4.w * b4.w);
                stcs4(oV + 4 * k, v);
                if (!diag) stcs4(oM + 4 * k, v);
            }
        }

        // ---- GEMM: warp w -> rows (i0=2w, j_g) and (i1=2w+1, j_g) ----
        const float* sXi0 = sXI + (2 * wid) * 72;
        const float* sXi1 = sXi0 + 72;

        float acc[8][4];
        #pragma unroll
        for (int nt = 0; nt < 8; nt++)
            #pragma unroll
            for (int r = 0; r < 4; r++) acc[nt][r] = 0.0f;

        #pragma unroll
        for (int ks = 0; ks < 4; ks++) {
            const int kc = ks * 16 + 2 * q;
            const float2 xa0 = *reinterpret_cast<const float2*>(sXi0 + kc);
            const float2 xc0 = *reinterpret_cast<const float2*>(sXi0 + kc + 8);
            const float2 xa1 = *reinterpret_cast<const float2*>(sXi1 + kc);
            const float2 xc1 = *reinterpret_cast<const float2*>(sXi1 + kc + 8);

            const float4 f0 = *reinterpret_cast<const float4*>(smem + OFF_EJ + swz8(g, q, ks));
            uint32_t ah[4], al[4];
            split2(f0.x * xa0.x, f0.y * xa0.y, ah[0], al[0]);   // row g   (i0), k-lo
            split2(f0.x * xa1.x, f0.y * xa1.y, ah[1], al[1]);   // row g+8 (i1), k-lo
            split2(f0.z * xc0.x, f0.w * xc0.y, ah[2], al[2]);   // row g   (i0), k-hi
            split2(f0.z * xc1.x, f0.w * xc1.y, ah[3], al[3]);   // row g+8 (i1), k-hi

            #pragma unroll
            for (int nt = 0; nt < 8; nt++) {
                const uint4 bv = *reinterpret_cast<const uint4*>(
                    smem + OFF_SB + swzoff(nt * 8 + g, q, ks));
                uint32_t bh[2] = {bv.x, bv.y};
                uint32_t bl[2] = {bv.z, bv.w};
                mma_bf16(acc[nt], ah, bh);
                mma_bf16(acc[nt], ah, bl);
                mma_bf16(acc[nt], al, bh);
            }
        }

        // ---- epilogue: logits for rows (i0,j_g) [h=0] and (i1,j_g) [h=1] ----
        #pragma unroll
        for (int h = 0; h < 2; h++) {
            float pl = 0.0f;
            #pragma unroll
            for (int nt = 0; nt < 8; nt++) {
                const int e0 = nt * 8 + 2 * q;
                float q0 = acc[nt][2 * h + 0] + sWB[e0];
                float q1 = acc[nt][2 * h + 1] + sWB[e0 + 1];
                q0 = (q0 >= 0.0f) ? q0 : NEG_SLOPE * q0;
                q1 = (q1 >= 0.0f) ? q1 : NEG_SLOPE * q1;
                pl = fmaf(sAW[e0], q0, pl);
                pl = fmaf(sAW[e0 + 1], q1, pl);
            }
            pl += __shfl_xor_sync(0xffffffffu, pl, 1);
            pl += __shfl_xor_sync(0xffffffffu, pl, 2);
            if (q == 0) {
                const int iG = bi * 8 + 2 * wid + h;
                const int jG = bj * 8 + g;
                logits[((size_t)b * Nn + iG) * Nn + jG] = pl;
                if (!diag) logits[((size_t)b * Nn + jG) * Nn + iG] = pl;
            }
        }
        __syncthreads();   // protect next block's fills
    }
}

// in-place softmax over last dim of logits [B,N,N]; warp per (b,i) row
__global__ __launch_bounds__(128)
void afm_softmax(float* __restrict__ logits)
{
    const int i = blockIdx.x * 4 + (threadIdx.x >> 5);
    const int b = blockIdx.y;
    const int lid = threadIdx.x & 31;
    float* row = logits + ((size_t)b * Nn + i) * Nn;
    float v0 = row[lid];
    float v1 = row[lid + 32];
    float m = fmaxf(v0, v1);
    #pragma unroll
    for (int msk = 16; msk >= 1; msk >>= 1)
        m = fmaxf(m, __shfl_xor_sync(0xffffffffu, m, msk));
    float e0 = __expf(v0 - m);
    float e1 = __expf(v1 - m);
    float s = e0 + e1;
    #pragma unroll
    for (int msk = 16; msk >= 1; msk >>= 1)
        s += __shfl_xor_sync(0xffffffffu, s, msk);
    const float inv = 1.0f / s;
    row[lid]      = e0 * inv;
    row[lid + 32] = e1 * inv;
}

extern "C" void kernel_launch(void* const* d_in, const int* in_sizes, int n_in,
                              void* d_out, int out_size)
{
    (void)in_sizes; (void)n_in; (void)out_size;
    const float* emb = (const float*)d_in[0];
    const float* wW  = (const float*)d_in[1];
    const float* wb  = (const float*)d_in[2];
    const float* aW  = (const float*)d_in[3];
    // d_in[4] = a_b: constant shift, cancels in softmax

    float* out  = (float*)d_out;
    float* outA = out;                          // logits scratch -> alphas
    float* outV = out + (size_t)Bn * Nn * Nn;

    cudaFuncSetAttribute(afm_pair, cudaFuncAttributeMaxDynamicSharedMemorySize, SMEM_TOTAL);
    dim3 grid1(9, Bn);
    afm_pair<<<grid1, 128, SMEM_TOTAL>>>(emb, wW, wb, aW, outA, outV);
    dim3 grid2(16, Bn);
    afm_softmax<<<grid2, 128>>>(outA);
}

// round 14
// speedup vs baseline: 1.1209x; 1.0646x over previous
#include <cuda_runtime.h>
#include <cuda_bf16.h>
#include <cstdint>

// Problem: B=256, N=64, d=64. Outputs concatenated: alphas [B,N,N,1] then value [B,N,N,64].
constexpr int Bn = 256;
constexpr int Nn = 64;
constexpr int Dn = 64;
constexpr float NEG_SLOPE = 0.01f;

// smem layout (bytes)
constexpr int OFF_WB = 0;                        // 64 f32
constexpr int OFF_AW = 256;                      // 64 f32
constexpr int OFF_XI = 512;                      // 2 blk x 8 i-rows fp32 stride 72: 4608
constexpr int OFF_XJ = 5120;                     // 2 blk x 8 j-rows: 4608
constexpr int OFF_EJ = 9728;                     // 2 blk x EJ frag table (swizzled): 4096
constexpr int OFF_SB = 13824;                    // W frag table bf16 hi/lo (swizzled): 16384
constexpr int SMEM_TOTAL = OFF_SB + 16384;       // 30208 B

// upper-triangle 8x8-block enumeration (36 blocks)
static __device__ const unsigned char cBI[36] = {
    0,0,0,0,0,0,0,0, 1,1,1,1,1,1,1, 2,2,2,2,2,2, 3,3,3,3,3, 4,4,4,4, 5,5,5, 6,6, 7};
static __device__ const unsigned char cBJ[36] = {
    0,1,2,3,4,5,6,7, 1,2,3,4,5,6,7, 2,3,4,5,6,7, 3,4,5,6,7, 4,5,6,7, 5,6,7, 6,7, 7};

static __device__ __forceinline__ void mma_bf16(float* c, const uint32_t* a, const uint32_t* b) {
    asm volatile(
        "mma.sync.aligned.m16n8k16.row.col.f32.bf16.bf16.f32 "
        "{%0,%1,%2,%3}, {%4,%5,%6,%7}, {%8,%9}, {%0,%1,%2,%3};"
        : "+f"(c[0]), "+f"(c[1]), "+f"(c[2]), "+f"(c[3])
        : "r"(a[0]), "r"(a[1]), "r"(a[2]), "r"(a[3]), "r"(b[0]), "r"(b[1]));
}

static __device__ __forceinline__ void split2(float a, float b, uint32_t& hi, uint32_t& lo) {
    __nv_bfloat162 h = __floats2bfloat162_rn(a, b);
    uint32_t hu = *reinterpret_cast<uint32_t*>(&h);
    float hax = __uint_as_float(hu << 16);
    float hay = __uint_as_float(hu & 0xFFFF0000u);
    __nv_bfloat162 l = __floats2bfloat162_rn(a - hax, b - hay);
    hi = hu;
    lo = *reinterpret_cast<uint32_t*>(&l);
}

static __device__ __forceinline__ void stcs4(float* p, float4 v) {
    asm volatile("st.global.cs.v4.f32 [%0], {%1,%2,%3,%4};"
                 :: "l"(p), "f"(v.x), "f"(v.y), "f"(v.z), "f"(v.w) : "memory");
}

// 64-row frag table swizzle (W table): ks block stride 4096B
static __device__ __forceinline__ uint32_t swzoff(int j, int q, int ks) {
    uint32_t u = (uint32_t)(j * 4 + q);
    uint32_t t = (((uint32_t)j & 3u) << 1) | (((uint32_t)ks >> 1) & 1u);
    return ((uint32_t)ks << 12) + ((u ^ t) << 4);
}
// 8-row frag table swizzle (EJ tables): ks block stride 512B
static __device__ __forceinline__ uint32_t swz8(int j, int q, int ks) {
    uint32_t u = (uint32_t)(j * 4 + q);
    uint32_t t = (((uint32_t)j & 3u) << 1) | (((uint32_t)ks >> 1) & 1u);
    return ((uint32_t)ks << 9) + ((u ^ t) << 4);
}

// One CTA: (b, 6 triangle blocks xb*6..xb*6+5). 256 threads / 8 warps.
// W frag table once per CTA. 3 passes; pass pp handles 2 blocks:
// warps 0-3 -> block A, warps 4-7 -> block B (each 4-warp group = R13 engine).
__global__ __launch_bounds__(256, 3)
void afm_pair(const float* __restrict__ emb,
              const float* __restrict__ wW,
              const float* __restrict__ wb,
              const float* __restrict__ aW,
              float* __restrict__ logits,   // B*N*N scratch (= alphas buffer)
              float* __restrict__ outV)
{
    extern __shared__ __align__(16) char smem[];
    const int xb  = blockIdx.x;   // 0..5
    const int b   = blockIdx.y;   // 0..255
    const int tx  = threadIdx.x;
    const int wid = tx >> 5;      // 0..7
    const int lid = tx & 31;
    const int g   = lid >> 2;     // 0..7
    const int q   = lid & 3;      // 0..3

    float* sWB = reinterpret_cast<float*>(smem + OFF_WB);
    float* sAW = reinterpret_cast<float*>(smem + OFF_AW);

    const float* embB = emb + (size_t)b * Nn * Dn;

    if (tx < 64) { sWB[tx] = wb[tx]; sAW[tx] = aW[tx]; }

    // ---- W frag table (64 rows), bf16 hi/lo, swizzled — ONCE per CTA ----
    {
        const int jr = tx >> 2;    // 0..63
        const int qt = tx & 3;     // ks block
        const float4* src = reinterpret_cast<const float4*>(wW + jr * Dn + qt * 16);
        uint32_t hu[8], lu[8];
        #pragma unroll
        for (int k = 0; k < 4; k++) {
            float4 w4 = src[k];
            split2(w4.x, w4.y, hu[2 * k],     lu[2 * k]);
            split2(w4.z, w4.w, hu[2 * k + 1], lu[2 * k + 1]);
        }
        #pragma unroll
        for (int qq = 0; qq < 4; qq++) {
            *reinterpret_cast<uint4*>(smem + OFF_SB + swzoff(jr, qq, qt)) =
                make_uint4(hu[qq], hu[qq + 4], lu[qq], lu[qq + 4]);
        }
    }

    #pragma unroll 1
    for (int pp = 0; pp < 3; pp++) {
        __syncthreads();   // protect tables from previous pass

        // ---- fills for both blocks of this pass ----
        {   // XI/XJ: blk = tx>>7, row = (tx>>4)&7, c4 = tx&15
            const int blk = tx >> 7;
            const int t   = xb * 6 + 2 * pp + blk;
            const int bi  = cBI[t];
            const int bj  = cBJ[t];
            const int row = (tx >> 4) & 7;
            const int c4  = tx & 15;
            float* sXI = reinterpret_cast<float*>(smem + OFF_XI + blk * 2304);
            float* sXJ = reinterpret_cast<float*>(smem + OFF_XJ + blk * 2304);
            reinterpret_cast<float4*>(sXI + row * 72)[c4] =
                reinterpret_cast<const float4*>(embB + (bi * 8 + row) * Dn)[c4];
            reinterpret_cast<float4*>(sXJ + row * 72)[c4] =
                reinterpret_cast<const float4*>(embB + (bj * 8 + row) * Dn)[c4];
        }
        if (tx < 64) {   // EJ frag tables: blk = tx>>5, row = (tx>>2)&7, qt = tx&3
            const int blk = tx >> 5;
            const int t   = xb * 6 + 2 * pp + blk;
            const int bj  = cBJ[t];
            const int row = (tx >> 2) & 7;
            const int qt  = tx & 3;
            float4 e[4];
            const float4* src = reinterpret_cast<const float4*>(
                embB + (bj * 8 + row) * Dn + qt * 16);
            #pragma unroll
            for (int k = 0; k < 4; k++) e[k] = src[k];
            #pragma unroll
            for (int qq = 0; qq < 4; qq++) {
                float4 va = e[qq >> 1];
                float4 vb = e[2 + (qq >> 1)];
                float ax = (qq & 1) ? va.z : va.x;
                float ay = (qq & 1) ? va.w : va.y;
                float bx = (qq & 1) ? vb.z : vb.x;
                float by = (qq & 1) ? vb.w : vb.y;
                *reinterpret_cast<float4*>(
                    smem + OFF_EJ + blk * 2048 + swz8(row, qq, qt)) =
                    make_float4(ax, ay, bx, by);
            }
        }
        __syncthreads();

        // ---- value phase: thread handles its block's pair (r, hf) ----
        {
            const int blk = tx >> 7;
            const int t   = xb * 6 + 2 * pp + blk;
            const int bi  = cBI[t];
            const int bj  = cBJ[t];
            const bool diag = (bi == bj);
            const int r  = (tx >> 1) & 63;
            const int hf = tx & 1;
            const int i  = r >> 3;
            const int j  = r & 7;
            const int iG = bi * 8 + i;
            const int jG = bj * 8 + j;
            const float* sXI = reinterpret_cast<const float*>(smem + OFF_XI + blk * 2304);
            const float* sXJ = reinterpret_cast<const float*>(smem + OFF_XJ + blk * 2304);
            const float4* xj = reinterpret_cast<const float4*>(sXJ + j * 72 + hf * 32);
            const float4* xi = reinterpret_cast<const float4*>(sXI + i * 72 + hf * 32);
            float* oV = outV + ((((size_t)b * Nn + iG) * Nn + jG) * Dn + hf * 32);
            float* oM = outV + ((((size_t)b * Nn + jG) * Nn + iG) * Dn + hf * 32);
            #pragma unroll
            for (int k = 0; k < 8; k++) {
                float4 a4 = xj[k];
                float4 b4 = xi[k];
                float4 v = make_float4(a4.x * b4.x, a4.y * b4.y, a4.z * b4.z, a4.w * b4.w);
                stcs4(oV + 4 * k, v);
                if (!diag) stcs4(oM + 4 * k, v);
            }
        }

        // ---- GEMM: warp group blk = wid>>2; warp w2 = wid&3 -> i-pair (2w2,2w2+1) x 8 j ----
        {
            const int blk = wid >> 2;
            const int w2  = wid & 3;
            const int t   = xb * 6 + 2 * pp + blk;
            const int bi  = cBI[t];
            const int bj  = cBJ[t];
            const bool diag = (bi == bj);
            const float* sXI = reinterpret_cast<const float*>(smem + OFF_XI + blk * 2304);
            const char*  sEJ = smem + OFF_EJ + blk * 2048;
            const float* sXi0 = sXI + (2 * w2) * 72;
            const float* sXi1 = sXi0 + 72;

            float acc[8][4];
            #pragma unroll
            for (int nt = 0; nt < 8; nt++)
                #pragma unroll
                for (int r = 0; r < 4; r++) acc[nt][r] = 0.0f;

            #pragma unroll
            for (int ks = 0; ks < 4; ks++) {
                const int kc = ks * 16 + 2 * q;
                const float2 xa0 = *reinterpret_cast<const float2*>(sXi0 + kc);
                const float2 xc0 = *reinterpret_cast<const float2*>(sXi0 + kc + 8);
                const float2 xa1 = *reinterpret_cast<const float2*>(sXi1 + kc);
                const float2 xc1 = *reinterpret_cast<const float2*>(sXi1 + kc + 8);

                const float4 f0 = *reinterpret_cast<const float4*>(sEJ + swz8(g, q, ks));
                uint32_t ah[4], al[4];
                split2(f0.x * xa0.x, f0.y * xa0.y, ah[0], al[0]);   // row g   (i0), k-lo
                split2(f0.x * xa1.x, f0.y * xa1.y, ah[1], al[1]);   // row g+8 (i1), k-lo
                split2(f0.z * xc0.x, f0.w * xc0.y, ah[2], al[2]);   // row g   (i0), k-hi
                split2(f0.z * xc1.x, f0.w * xc1.y, ah[3], al[3]);   // row g+8 (i1), k-hi

                #pragma unroll
                for (int nt = 0; nt < 8; nt++) {
                    const uint4 bv = *reinterpret_cast<const uint4*>(
                        smem + OFF_SB + swzoff(nt * 8 + g, q, ks));
                    uint32_t bh[2] = {bv.x, bv.y};
                    uint32_t bl[2] = {bv.z, bv.w};
                    mma_bf16(acc[nt], ah, bh);
                    mma_bf16(acc[nt], ah, bl);
                    mma_bf16(acc[nt], al, bh);
                }
            }

            // ---- epilogue: logits rows (i0,j_g) [h=0], (i1,j_g) [h=1] ----
            #pragma unroll
            for (int h = 0; h < 2; h++) {
                float pl = 0.0f;
                #pragma unroll
                for (int nt = 0; nt < 8; nt++) {
                    const int e0 = nt * 8 + 2 * q;
                    float q0 = acc[nt][2 * h + 0] + sWB[e0];
                    float q1 = acc[nt][2 * h + 1] + sWB[e0 + 1];
                    q0 = (q0 >= 0.0f) ? q0 : NEG_SLOPE * q0;
                    q1 = (q1 >= 0.0f) ? q1 : NEG_SLOPE * q1;
                    pl = fmaf(sAW[e0], q0, pl);
                    pl = fmaf(sAW[e0 + 1], q1, pl);
                }
                pl += __shfl_xor_sync(0xffffffffu, pl, 1);
                pl += __shfl_xor_sync(0xffffffffu, pl, 2);
                if (q == 0) {
                    const int iG = bi * 8 + 2 * w2 + h;
                    const int jG = bj * 8 + g;
                    logits[((size_t)b * Nn + iG) * Nn + jG] = pl;
                    if (!diag) logits[((size_t)b * Nn + jG) * Nn + iG] = pl;
                }
            }
        }
    }
}

// in-place softmax over last dim of logits [B,N,N]; warp per (b,i) row
__global__ __launch_bounds__(128)
void afm_softmax(float* __restrict__ logits)
{
    const int i = blockIdx.x * 4 + (threadIdx.x >> 5);
    const int b = blockIdx.y;
    const int lid = threadIdx.x & 31;
    float* row = logits + ((size_t)b * Nn + i) * Nn;
    float v0 = row[lid];
    float v1 = row[lid + 32];
    float m = fmaxf(v0, v1);
    #pragma unroll
    for (int msk = 16; msk >= 1; msk >>= 1)
        m = fmaxf(m, __shfl_xor_sync(0xffffffffu, m, msk));
    float e0 = __expf(v0 - m);
    float e1 = __expf(v1 - m);
    float s = e0 + e1;
    #pragma unroll
    for (int msk = 16; msk >= 1; msk >>= 1)
        s += __shfl_xor_sync(0xffffffffu, s, msk);
    const float inv = 1.0f / s;
    row[lid]      = e0 * inv;
    row[lid + 32] = e1 * inv;
}

extern "C" void kernel_launch(void* const* d_in, const int* in_sizes, int n_in,
                              void* d_out, int out_size)
{
    (void)in_sizes; (void)n_in; (void)out_size;
    const float* emb = (const float*)d_in[0];
    const float* wW  = (const float*)d_in[1];
    const float* wb  = (const float*)d_in[2];
    const float* aW  = (const float*)d_in[3];
    // d_in[4] = a_b: constant shift, cancels in softmax

    float* out  = (float*)d_out;
    float* outA = out;                          // logits scratch -> alphas
    float* outV = out + (size_t)Bn * Nn * Nn;

    cudaFuncSetAttribute(afm_pair, cudaFuncAttributeMaxDynamicSharedMemorySize, SMEM_TOTAL);
    dim3 grid1(6, Bn);
    afm_pair<<<grid1, 256, SMEM_TOTAL>>>(emb, wW, wb, aW, outA, outV);
    dim3 grid2(16, Bn);
    afm_softmax<<<grid2, 128>>>(outA);
}

// round 15
// speedup vs baseline: 1.6964x; 1.5134x over previous
#include <cuda_runtime.h>
#include <cuda_bf16.h>
#include <cstdint>

// Problem: B=256, N=64, d=64. Outputs concatenated: alphas [B,N,N,1] then value [B,N,N,64].
constexpr int Bn = 256;
constexpr int Nn = 64;
constexpr int Dn = 64;
constexpr float NEG_SLOPE = 0.01f;

// dynamic smem layout (bytes)
constexpr int OFF_WB  = 0;                       // 64 f32
constexpr int OFF_AW  = 256;                     // 64 f32
constexpr int OFF_LOG = 512;                     // 512 f32 (8 i's x 64 logits) = 2048
constexpr int OFF_XI  = 2560;                    // 8 i-rows natural fp32, stride 72: 2304
constexpr int OFF_SF  = 4992;                    // E frag table fp32 (swizzled): 16384
constexpr int OFF_SB  = OFF_SF + 16384;          // W frag table bf16 hi/lo (swizzled): 16384
constexpr int SMEM_TOTAL = OFF_SB + 16384;       // 37760 B

static __device__ __forceinline__ void mma_bf16(float* c, const uint32_t* a, const uint32_t* b) {
    asm volatile(
        "mma.sync.aligned.m16n8k16.row.col.f32.bf16.bf16.f32 "
        "{%0,%1,%2,%3}, {%4,%5,%6,%7}, {%8,%9}, {%0,%1,%2,%3};"
        : "+f"(c[0]), "+f"(c[1]), "+f"(c[2]), "+f"(c[3])
        : "r"(a[0]), "r"(a[1]), "r"(a[2]), "r"(a[3]), "r"(b[0]), "r"(b[1]));
}

// split fp32 pair -> packed bf16x2 hi and bf16x2 lo (lo via bit-extracted hi)
static __device__ __forceinline__ void split2(float a, float b, uint32_t& hi, uint32_t& lo) {
    __nv_bfloat162 h = __floats2bfloat162_rn(a, b);
    uint32_t hu = *reinterpret_cast<uint32_t*>(&h);
    float hax = __uint_as_float(hu << 16);
    float hay = __uint_as_float(hu & 0xFFFF0000u);
    __nv_bfloat162 l = __floats2bfloat162_rn(a - hax, b - hay);
    hi = hu;
    lo = *reinterpret_cast<uint32_t*>(&l);
}

static __device__ __forceinline__ void stcs4(float* p, float4 v) {
    asm volatile("st.global.cs.v4.f32 [%0], {%1,%2,%3,%4};"
                 :: "l"(p), "f"(v.x), "f"(v.y), "f"(v.z), "f"(v.w) : "memory");
}

// swizzled byte offset of 16B unit (j*4+q) inside ks-block of a frag table.
static __device__ __forceinline__ uint32_t swzoff(int j, int q, int ks) {
    uint32_t u = (uint32_t)(j * 4 + q);
    uint32_t t = (((uint32_t)j & 3u) << 1) | (((uint32_t)ks >> 1) & 1u);
    return ((uint32_t)ks << 12) + ((u ^ t) << 4);
}

// One CTA: (b, i0..i7 = 8*ib..8*ib+7), 256 threads / 8 warps.
// Shared E fp32 frag table + W bf16 frag table filled once.
// Value phase: fully coalesced 512B/warp stores; E via L1-hot coalesced LDG.
// 4 GEMM passes; pass p: warps 0-3 -> i(2p), warps 4-7 -> i(2p+1).
__global__ __launch_bounds__(256, 3)
void afm_mma(const float* __restrict__ emb,
             const float* __restrict__ wW,
             const float* __restrict__ wb,
             const float* __restrict__ aW,
             float* __restrict__ outA,
             float* __restrict__ outV)
{
    extern __shared__ __align__(16) char smem[];
    const int ib  = blockIdx.x;   // 0..7
    const int b   = blockIdx.y;   // 0..255
    const int tx  = threadIdx.x;
    const int wid = tx >> 5;      // 0..7
    const int lid = tx & 31;
    const int g   = lid >> 2;     // 0..7
    const int q   = lid & 3;      // 0..3

    float* sWB  = reinterpret_cast<float*>(smem + OFF_WB);
    float* sAW  = reinterpret_cast<float*>(smem + OFF_AW);
    float* sLOG = reinterpret_cast<float*>(smem + OFF_LOG);
    float* sXI  = reinterpret_cast<float*>(smem + OFF_XI);

    const int jr = tx >> 2;       // row 0..63 this thread fills
    const int qt = tx & 3;        // 16-float quarter of the row (= ks block)

    const float* embB = emb + (size_t)b * Nn * Dn;
    const float4* embB4 = reinterpret_cast<const float4*>(embB);

    if (tx < 64) { sWB[tx] = wb[tx]; sAW[tx] = aW[tx]; }
    // natural-order copy of the CTA's 8 i-rows (8 rows x 16 float4 = 128 float4)
    if (tx < 128) {
        const int row = tx >> 4;   // 0..7
        const int c4  = tx & 15;
        reinterpret_cast<float4*>(sXI + row * 72)[c4] =
            reinterpret_cast<const float4*>(embB + (8 * ib + row) * Dn)[c4];
    }

    // ---- fill: emb quarter-row -> sF (swizzled fp32 frag table) ----
    {
        float4 ereg[4];
        const float4* src = reinterpret_cast<const float4*>(embB + jr * Dn + qt * 16);
        #pragma unroll
        for (int k = 0; k < 4; k++) ereg[k] = src[k];
        #pragma unroll
        for (int qq = 0; qq < 4; qq++) {
            float4 va = ereg[qq >> 1];
            float4 vb = ereg[2 + (qq >> 1)];
            float ax = (qq & 1) ? va.z : va.x;
            float ay = (qq & 1) ? va.w : va.y;
            float bx = (qq & 1) ? vb.z : vb.x;
            float by = (qq & 1) ? vb.w : vb.y;
            *reinterpret_cast<float4*>(smem + OFF_SF + swzoff(jr, qq, qt)) =
                make_float4(ax, ay, bx, by);
        }
    }

    // ---- fill: W quarter-row -> bf16 hi/lo splits -> sB frag table ----
    {
        const float4* src = reinterpret_cast<const float4*>(wW + jr * Dn + qt * 16);
        uint32_t hu[8], lu[8];
        #pragma unroll
        for (int k = 0; k < 4; k++) {
            float4 w4 = src[k];
            split2(w4.x, w4.y, hu[2 * k],     lu[2 * k]);
            split2(w4.z, w4.w, hu[2 * k + 1], lu[2 * k + 1]);
        }
        #pragma unroll
        for (int qq = 0; qq < 4; qq++) {
            *reinterpret_cast<uint4*>(smem + OFF_SB + swzoff(jr, qq, qt)) =
                make_uint4(hu[qq], hu[qq + 4], lu[qq], lu[qq + 4]);
        }
    }
    __syncthreads();

    // ---- value phase (fully coalesced): lane = (row parity h, 16B chunk c) ----
    // warp writes 2 complete rows = 512B contiguous per store instruction.
    {
        const int c = lid & 15;    // 16B chunk within row (d = 4c..4c+3)
        const int h = lid >> 4;    // row parity within warp
        #pragma unroll
        for (int it = 0; it < 4; it++) {
            const int r = it * 16 + wid * 2 + h;       // j row 0..63
            const float4 e = embB4[r * 16 + c];        // coalesced, L1-hot
            #pragma unroll
            for (int L = 0; L < 8; L++) {
                const float4 xi = *reinterpret_cast<const float4*>(sXI + L * 72 + c * 4);
                float* oV = outV +
                    ((((size_t)b * Nn + 8 * ib + L) * Nn + r) * Dn + c * 4);
                stcs4(oV, make_float4(e.x * xi.x, e.y * xi.y, e.z * xi.z, e.w * xi.w));
            }
        }
    }

    // ---- GEMM passes: per i, D[64x64] = (E*x_i) @ W^T, 3-term bf16 emulation ----
    const int jw = (wid & 3) * 16;                 // this warp's 16 j-rows

    #pragma unroll
    for (int p = 0; p < 4; p++) {
        const int iLocal = 2 * p + (wid >> 2);     // this warp's i (0..7)
        const float* sXiN = sXI + iLocal * 72;

        float acc[8][4];
        #pragma unroll
        for (int nt = 0; nt < 8; nt++)
            #pragma unroll
            for (int r = 0; r < 4; r++) acc[nt][r] = 0.0f;

        #pragma unroll
        for (int ks = 0; ks < 4; ks++) {
            const int kc = ks * 16 + 2 * q;
            const float2 xa = *reinterpret_cast<const float2*>(sXiN + kc);
            const float2 xb = *reinterpret_cast<const float2*>(sXiN + kc + 8);

            uint32_t ah[4], al[4];
            {
                const float4 f0 = *reinterpret_cast<const float4*>(
                    smem + OFF_SF + swzoff(jw + g, q, ks));
                const float4 f1 = *reinterpret_cast<const float4*>(
                    smem + OFF_SF + swzoff(jw + g + 8, q, ks));
                split2(f0.x * xa.x, f0.y * xa.y, ah[0], al[0]);
                split2(f1.x * xa.x, f1.y * xa.y, ah[1], al[1]);
                split2(f0.z * xb.x, f0.w * xb.y, ah[2], al[2]);
                split2(f1.z * xb.x, f1.w * xb.y, ah[3], al[3]);
            }
            #pragma unroll
            for (int nt = 0; nt < 8; nt++) {
                const uint4 bv = *reinterpret_cast<const uint4*>(
                    smem + OFF_SB + swzoff(nt * 8 + g, q, ks));
                uint32_t bh[2] = {bv.x, bv.y};
                uint32_t bl[2] = {bv.z, bv.w};
                mma_bf16(acc[nt], ah, bh);
                mma_bf16(acc[nt], ah, bl);
                mma_bf16(acc[nt], al, bh);
            }
        }

        // ---- epilogue: bias + LeakyReLU + dot(aW) -> logits for this pass ----
        #pragma unroll
        for (int half = 0; half < 2; half++) {
            float pl = 0.0f;
            #pragma unroll
            for (int nt = 0; nt < 8; nt++) {
                const int e0 = nt * 8 + 2 * q;
                float q0 = acc[nt][half * 2 + 0] + sWB[e0];
                float q1 = acc[nt][half * 2 + 1] + sWB[e0 + 1];
                q0 = (q0 >= 0.0f) ? q0 : NEG_SLOPE * q0;
                q1 = (q1 >= 0.0f) ? q1 : NEG_SLOPE * q1;
                pl = fmaf(sAW[e0], q0, pl);
                pl = fmaf(sAW[e0 + 1], q1, pl);
            }
            pl += __shfl_xor_sync(0xffffffffu, pl, 1);
            pl += __shfl_xor_sync(0xffffffffu, pl, 2);
            if (q == 0) sLOG[iLocal * 64 + jw + half * 8 + g] = pl;  // disjoint per pass
        }
    }
    __syncthreads();

    // ---- softmax per i over 64 j's: warp w -> i = w ----
    {
        const int iL = wid;
        float v0 = sLOG[iL * 64 + lid];
        float v1 = sLOG[iL * 64 + lid + 32];
        float m = fmaxf(v0, v1);
        #pragma unroll
        for (int msk = 16; msk >= 1; msk >>= 1)
            m = fmaxf(m, __shfl_xor_sync(0xffffffffu, m, msk));
        float e0 = __expf(v0 - m);
        float e1 = __expf(v1 - m);
        float s = e0 + e1;
        #pragma unroll
        for (int msk = 16; msk >= 1; msk >>= 1)
            s += __shfl_xor_sync(0xffffffffu, s, msk);
        const float inv = 1.0f / s;
        const int iGlob = 8 * ib + iL;
        float* oa = outA + ((size_t)b * Nn + iGlob) * Nn;
        oa[lid]      = e0 * inv;
        oa[lid + 32] = e1 * inv;
    }
}

extern "C" void kernel_launch(void* const* d_in, const int* in_sizes, int n_in,
                              void* d_out, int out_size)
{
    (void)in_sizes; (void)n_in; (void)out_size;
    const float* emb = (const float*)d_in[0];
    const float* wW  = (const float*)d_in[1];
    const float* wb  = (const float*)d_in[2];
    const float* aW  = (const float*)d_in[3];
    // d_in[4] = a_b: constant shift, cancels in softmax

    float* out  = (float*)d_out;
    float* outA = out;
    float* outV = out + (size_t)Bn * Nn * Nn;

    cudaFuncSetAttribute(afm_mma, cudaFuncAttributeMaxDynamicSharedMemorySize, SMEM_TOTAL);
    dim3 grid(Nn / 8, Bn);
    afm_mma<<<grid, 256, SMEM_TOTAL>>>(emb, wW, wb, aW, outA, outV);
}

// round 16
// speedup vs baseline: 2.1397x; 1.2613x over previous
#include <cuda_runtime.h>
#include <cuda_bf16.h>
#include <cstdint>

// Problem: B=256, N=64, d=64. Outputs concatenated: alphas [B,N,N,1] then value [B,N,N,64].
constexpr int Bn = 256;
constexpr int Nn = 64;
constexpr int Dn = 64;
constexpr float NEG_SLOPE = 0.01f;

// smem layout (bytes)
constexpr int OFF_WB = 0;                        // 64 f32
constexpr int OFF_AW = 256;                      // 64 f32
constexpr int OFF_LT = 512;                      // 2 blk x 64 f32 logit tiles: 512
constexpr int OFF_XI = 1024;                     // 2 blk x 8 i-rows fp32 stride 72: 4608
constexpr int OFF_XJ = 5632;                     // 2 blk x 8 j-rows: 4608
constexpr int OFF_EJ = 10240;                    // 2 blk x EJ frag table (swizzled): 4096
constexpr int OFF_SB = 14336;                    // W frag table bf16 hi/lo (swizzled): 16384
constexpr int SMEM_TOTAL = OFF_SB + 16384;       // 30720 B

// upper-triangle 8x8-block enumeration (36 blocks)
static __device__ const unsigned char cBI[36] = {
    0,0,0,0,0,0,0,0, 1,1,1,1,1,1,1, 2,2,2,2,2,2, 3,3,3,3,3, 4,4,4,4, 5,5,5, 6,6, 7};
static __device__ const unsigned char cBJ[36] = {
    0,1,2,3,4,5,6,7, 1,2,3,4,5,6,7, 2,3,4,5,6,7, 3,4,5,6,7, 4,5,6,7, 5,6,7, 6,7, 7};

static __device__ __forceinline__ void mma_bf16(float* c, const uint32_t* a, const uint32_t* b) {
    asm volatile(
        "mma.sync.aligned.m16n8k16.row.col.f32.bf16.bf16.f32 "
        "{%0,%1,%2,%3}, {%4,%5,%6,%7}, {%8,%9}, {%0,%1,%2,%3};"
        : "+f"(c[0]), "+f"(c[1]), "+f"(c[2]), "+f"(c[3])
        : "r"(a[0]), "r"(a[1]), "r"(a[2]), "r"(a[3]), "r"(b[0]), "r"(b[1]));
}

static __device__ __forceinline__ void split2(float a, float b, uint32_t& hi, uint32_t& lo) {
    __nv_bfloat162 h = __floats2bfloat162_rn(a, b);
    uint32_t hu = *reinterpret_cast<uint32_t*>(&h);
    float hax = __uint_as_float(hu << 16);
    float hay = __uint_as_float(hu & 0xFFFF0000u);
    __nv_bfloat162 l = __floats2bfloat162_rn(a - hax, b - hay);
    hi = hu;
    lo = *reinterpret_cast<uint32_t*>(&l);
}

static __device__ __forceinline__ void stcs4(float* p, float4 v) {
    asm volatile("st.global.cs.v4.f32 [%0], {%1,%2,%3,%4};"
                 :: "l"(p), "f"(v.x), "f"(v.y), "f"(v.z), "f"(v.w) : "memory");
}

// 64-row frag table swizzle (W table): ks block stride 4096B
static __device__ __forceinline__ uint32_t swzoff(int j, int q, int ks) {
    uint32_t u = (uint32_t)(j * 4 + q);
    uint32_t t = (((uint32_t)j & 3u) << 1) | (((uint32_t)ks >> 1) & 1u);
    return ((uint32_t)ks << 12) + ((u ^ t) << 4);
}
// 8-row frag table swizzle (EJ tables): ks block stride 512B
static __device__ __forceinline__ uint32_t swz8(int j, int q, int ks) {
    uint32_t u = (uint32_t)(j * 4 + q);
    uint32_t t = (((uint32_t)j & 3u) << 1) | (((uint32_t)ks >> 1) & 1u);
    return ((uint32_t)ks << 9) + ((u ^ t) << 4);
}

// One CTA: (b, 6 triangle blocks xb*6..xb*6+5). 256 threads / 8 warps, 3 passes x 2 blocks.
// W frag table once per CTA. Per block: coalesced value(+mirror) stores,
// M=16 GEMM (i-pair x 8 j) per warp, smem-staged logit tile(+mirror) to scratch.
__global__ __launch_bounds__(256, 3)
void afm_pair(const float* __restrict__ emb,
              const float* __restrict__ wW,
              const float* __restrict__ wb,
              const float* __restrict__ aW,
              float* __restrict__ logits,   // B*N*N scratch (= alphas buffer)
              float* __restrict__ outV)
{
    extern __shared__ __align__(16) char smem[];
    const int xb  = blockIdx.x;   // 0..5
    const int b   = blockIdx.y;   // 0..255
    const int tx  = threadIdx.x;
    const int wid = tx >> 5;      // 0..7
    const int lid = tx & 31;
    const int g   = lid >> 2;     // 0..7
    const int q   = lid & 3;      // 0..3

    float* sWB = reinterpret_cast<float*>(smem + OFF_WB);
    float* sAW = reinterpret_cast<float*>(smem + OFF_AW);
    float* sLT = reinterpret_cast<float*>(smem + OFF_LT);

    const float* embB = emb + (size_t)b * Nn * Dn;
    const float4* embB4 = reinterpret_cast<const float4*>(embB);

    if (tx < 64) { sWB[tx] = wb[tx]; sAW[tx] = aW[tx]; }

    // ---- W frag table (64 rows), bf16 hi/lo, swizzled — ONCE per CTA ----
    {
        const int jr = tx >> 2;    // 0..63
        const int qt = tx & 3;     // ks block
        const float4* src = reinterpret_cast<const float4*>(wW + jr * Dn + qt * 16);
        uint32_t hu[8], lu[8];
        #pragma unroll
        for (int k = 0; k < 4; k++) {
            float4 w4 = src[k];
            split2(w4.x, w4.y, hu[2 * k],     lu[2 * k]);
            split2(w4.z, w4.w, hu[2 * k + 1], lu[2 * k + 1]);
        }
        #pragma unroll
        for (int qq = 0; qq < 4; qq++) {
            *reinterpret_cast<uint4*>(smem + OFF_SB + swzoff(jr, qq, qt)) =
                make_uint4(hu[qq], hu[qq + 4], lu[qq], lu[qq + 4]);
        }
    }

    #pragma unroll 1
    for (int pp = 0; pp < 3; pp++) {
        __syncthreads();   // protect tables/tiles from previous pass

        // ---- fills for both blocks of this pass ----
        {   // XI/XJ: blk = tx>>7, row = (tx>>4)&7, c4 = tx&15
            const int blk = tx >> 7;
            const int t   = xb * 6 + 2 * pp + blk;
            const int bi  = cBI[t];
            const int bj  = cBJ[t];
            const int row = (tx >> 4) & 7;
            const int c4  = tx & 15;
            float* sXI = reinterpret_cast<float*>(smem + OFF_XI + blk * 2304);
            float* sXJ = reinterpret_cast<float*>(smem + OFF_XJ + blk * 2304);
            reinterpret_cast<float4*>(sXI + row * 72)[c4] =
                reinterpret_cast<const float4*>(embB + (bi * 8 + row) * Dn)[c4];
            reinterpret_cast<float4*>(sXJ + row * 72)[c4] =
                reinterpret_cast<const float4*>(embB + (bj * 8 + row) * Dn)[c4];
        }
        if (tx < 64) {   // EJ frag tables: blk = tx>>5, row = (tx>>2)&7, qt = tx&3
            const int blk = tx >> 5;
            const int t   = xb * 6 + 2 * pp + blk;
            const int bj  = cBJ[t];
            const int row = (tx >> 2) & 7;
            const int qt  = tx & 3;
            float4 e[4];
            const float4* src = reinterpret_cast<const float4*>(
                embB + (bj * 8 + row) * Dn + qt * 16);
            #pragma unroll
            for (int k = 0; k < 4; k++) e[k] = src[k];
            #pragma unroll
            for (int qq = 0; qq < 4; qq++) {
                float4 va = e[qq >> 1];
                float4 vb = e[2 + (qq >> 1)];
                float ax = (qq & 1) ? va.z : va.x;
                float ay = (qq & 1) ? va.w : va.y;
                float bx = (qq & 1) ? vb.z : vb.x;
                float by = (qq & 1) ? vb.w : vb.y;
                *reinterpret_cast<float4*>(
                    smem + OFF_EJ + blk * 2048 + swz8(row, qq, qt)) =
                    make_float4(ax, ay, bx, by);
            }
        }
        __syncthreads();

        const int blk = wid >> 2;           // this warp's block (0/1)
        const int w2  = wid & 3;
        const int t   = xb * 6 + 2 * pp + blk;
        const int bi  = cBI[t];
        const int bj  = cBJ[t];
        const bool diag = (bi == bj);
        const float* sXI = reinterpret_cast<const float*>(smem + OFF_XI + blk * 2304);
        const char*  sEJ = smem + OFF_EJ + blk * 2048;

        // ---- value phase (coalesced + coalesced mirror) ----
        // lane = (h = row parity, c = 16B chunk); warp owns j rows (2w2, 2w2+1).
        {
            const int c = lid & 15;
            const int h = lid >> 4;
            const int jloc = w2 * 2 + h;
            const int jG = bj * 8 + jloc;
            const float4 e = embB4[jG * 16 + c];     // 512B/warp, L1-hot
            #pragma unroll
            for (int L = 0; L < 8; L++) {
                const int iG = bi * 8 + L;
                const float4 xi = *reinterpret_cast<const float4*>(sXI + L * 72 + c * 4);
                const float4 v = make_float4(e.x * xi.x, e.y * xi.y, e.z * xi.z, e.w * xi.w);
                stcs4(outV + ((((size_t)b * Nn + iG) * Nn + jG) * Dn + c * 4), v);
                if (!diag)
                    stcs4(outV + ((((size_t)b * Nn + jG) * Nn + iG) * Dn + c * 4), v);
            }
        }

        // ---- GEMM: warp -> i-pair (2w2, 2w2+1) x 8 j (M=16), 3-term bf16 ----
        {
            const float* sXi0 = sXI + (2 * w2) * 72;
            const float* sXi1 = sXi0 + 72;

            float acc[8][4];
            #pragma unroll
            for (int nt = 0; nt < 8; nt++)
                #pragma unroll
                for (int r = 0; r < 4; r++) acc[nt][r] = 0.0f;

            #pragma unroll
            for (int ks = 0; ks < 4; ks++) {
                const int kc = ks * 16 + 2 * q;
                const float2 xa0 = *reinterpret_cast<const float2*>(sXi0 + kc);
                const float2 xc0 = *reinterpret_cast<const float2*>(sXi0 + kc + 8);
                const float2 xa1 = *reinterpret_cast<const float2*>(sXi1 + kc);
                const float2 xc1 = *reinterpret_cast<const float2*>(sXi1 + kc + 8);

                const float4 f0 = *reinterpret_cast<const float4*>(sEJ + swz8(g, q, ks));
                uint32_t ah[4], al[4];
                split2(f0.x * xa0.x, f0.y * xa0.y, ah[0], al[0]);   // row g   (i0), k-lo
                split2(f0.x * xa1.x, f0.y * xa1.y, ah[1], al[1]);   // row g+8 (i1), k-lo
                split2(f0.z * xc0.x, f0.w * xc0.y, ah[2], al[2]);   // row g   (i0), k-hi
                split2(f0.z * xc1.x, f0.w * xc1.y, ah[3], al[3]);   // row g+8 (i1), k-hi

                #pragma unroll
                for (int nt = 0; nt < 8; nt++) {
                    const uint4 bv = *reinterpret_cast<const uint4*>(
                        smem + OFF_SB + swzoff(nt * 8 + g, q, ks));
                    uint32_t bh[2] = {bv.x, bv.y};
                    uint32_t bl[2] = {bv.z, bv.w};
                    mma_bf16(acc[nt], ah, bh);
                    mma_bf16(acc[nt], ah, bl);
                    mma_bf16(acc[nt], al, bh);
                }
            }

            // ---- epilogue: logits -> smem tile [local i][local j] ----
            #pragma unroll
            for (int h = 0; h < 2; h++) {
                float pl = 0.0f;
                #pragma unroll
                for (int nt = 0; nt < 8; nt++) {
                    const int e0 = nt * 8 + 2 * q;
                    float q0 = acc[nt][2 * h + 0] + sWB[e0];
                    float q1 = acc[nt][2 * h + 1] + sWB[e0 + 1];
                    q0 = (q0 >= 0.0f) ? q0 : NEG_SLOPE * q0;
                    q1 = (q1 >= 0.0f) ? q1 : NEG_SLOPE * q1;
                    pl = fmaf(sAW[e0], q0, pl);
                    pl = fmaf(sAW[e0 + 1], q1, pl);
                }
                pl += __shfl_xor_sync(0xffffffffu, pl, 1);
                pl += __shfl_xor_sync(0xffffffffu, pl, 2);
                if (q == 0) sLT[blk * 64 + (2 * w2 + h) * 8 + g] = pl;
            }
        }
        __syncthreads();

        // ---- staged logit stores (coalesced 32B chunks) + mirror ----
        if (tx < 128) {
            const int sblk = tx >> 6;
            const int s    = tx & 63;
            const int i    = s >> 3;
            const int j    = s & 7;
            const int tt   = xb * 6 + 2 * pp + sblk;
            const int sbi  = cBI[tt];
            const int sbj  = cBJ[tt];
            const float pl = sLT[sblk * 64 + s];
            logits[((size_t)b * Nn + sbi * 8 + i) * Nn + sbj * 8 + j] = pl;
            if (sbi != sbj)
                logits[((size_t)b * Nn + sbj * 8 + j) * Nn + sbi * 8 + i] = pl;
        }
    }
}

// in-place softmax over last dim of logits [B,N,N]; warp per (b,i) row
__global__ __launch_bounds__(128)
void afm_softmax(float* __restrict__ logits)
{
    const int i = blockIdx.x * 4 + (threadIdx.x >> 5);
    const int b = blockIdx.y;
    const int lid = threadIdx.x & 31;
    float* row = logits + ((size_t)b * Nn + i) * Nn;
    float v0 = row[lid];
    float v1 = row[lid + 32];
    float m = fmaxf(v0, v1);
    #pragma unroll
    for (int msk = 16; msk >= 1; msk >>= 1)
        m = fmaxf(m, __shfl_xor_sync(0xffffffffu, m, msk));
    float e0 = __expf(v0 - m);
    float e1 = __expf(v1 - m);
    float s = e0 + e1;
    #pragma unroll
    for (int msk = 16; msk >= 1; msk >>= 1)
        s += __shfl_xor_sync(0xffffffffu, s, msk);
    const float inv = 1.0f / s;
    row[lid]      = e0 * inv;
    row[lid + 32] = e1 * inv;
}

extern "C" void kernel_launch(void* const* d_in, const int* in_sizes, int n_in,
                              void* d_out, int out_size)
{
    (void)in_sizes; (void)n_in; (void)out_size;
    const float* emb = (const float*)d_in[0];
    const float* wW  = (const float*)d_in[1];
    const float* wb  = (const float*)d_in[2];
    const float* aW  = (const float*)d_in[3];
    // d_in[4] = a_b: constant shift, cancels in softmax

    float* out  = (float*)d_out;
    float* outA = out;                          // logits scratch -> alphas
    float* outV = out + (size_t)Bn * Nn * Nn;

    cudaFuncSetAttribute(afm_pair, cudaFuncAttributeMaxDynamicSharedMemorySize, SMEM_TOTAL);
    dim3 grid1(6, Bn);
    afm_pair<<<grid1, 256, SMEM_TOTAL>>>(emb, wW, wb, aW, outA, outV);
    dim3 grid2(16, Bn);
    afm_softmax<<<grid2, 128>>>(outA);
}